// round 8
// baseline (speedup 1.0000x reference)
#include <cuda_runtime.h>
#include <cuda_fp16.h>
#include <stdint.h>

// RNN1DGeneral: B=16384, L=64, H=64, DEPTH=2, D_L=2, D_C=8, LPF=0.5
// R8: Wh1 + Win1 B-fragments pinned in registers (128 regs) across all 65
// steps; only Wh0 is re-read from SMEM each step (16 LDS.128, issued at the
// top of the iteration, hidden under 32 register-operand MMAs).

__device__ __forceinline__ void mmaf16(uint32_t& d0, uint32_t& d1,
    uint32_t a0, uint32_t a1, uint32_t a2, uint32_t a3,
    uint32_t b0, uint32_t b1)
{
    asm("mma.sync.aligned.m16n8k16.row.col.f16.f16.f16.f16 "
        "{%0,%1},{%2,%3,%4,%5},{%6,%7},{%0,%1};"
        : "+r"(d0), "+r"(d1)
        : "r"(a0), "r"(a1), "r"(a2), "r"(a3), "r"(b0), "r"(b1));
}

__device__ __forceinline__ void mmaf16_init(uint32_t& d0, uint32_t& d1,
    uint32_t a0, uint32_t a1, uint32_t a2, uint32_t a3,
    uint32_t b0, uint32_t b1, uint32_t c0, uint32_t c1)
{
    asm("mma.sync.aligned.m16n8k16.row.col.f16.f16.f16.f16 "
        "{%0,%1},{%2,%3,%4,%5},{%6,%7},{%8,%9};"
        : "=r"(d0), "=r"(d1)
        : "r"(a0), "r"(a1), "r"(a2), "r"(a3), "r"(b0), "r"(b1),
          "r"(c0), "r"(c1));
}

__device__ __forceinline__ uint32_t pack2(float lo, float hi) {
    __half2 h = __floats2half2_rn(lo, hi);
    return *reinterpret_cast<const uint32_t*>(&h);
}

// elementwise ELU on packed half2: max(v,0) + min(exp(v)-1, 0)
__device__ __forceinline__ uint32_t elu_h2(uint32_t u) {
    const uint32_t LOG2E2 = 0x3DC53DC5u;  // half2(log2e, log2e)
    const uint32_t ONE2   = 0x3C003C00u;  // half2(1, 1)
    uint32_t zero = 0u;
    uint32_t t, e, em1, mx, mn, r;
    asm("mul.rn.f16x2 %0, %1, %2;" : "=r"(t) : "r"(u), "r"(LOG2E2));
    asm("ex2.approx.f16x2 %0, %1;" : "=r"(e) : "r"(t));
    asm("sub.rn.f16x2 %0, %1, %2;" : "=r"(em1) : "r"(e), "r"(ONE2));
    asm("max.f16x2 %0, %1, %2;" : "=r"(mx) : "r"(u), "r"(zero));
    asm("min.f16x2 %0, %1, %2;" : "=r"(mn) : "r"(em1), "r"(zero));
    asm("add.rn.f16x2 %0, %1, %2;" : "=r"(r) : "r"(mx), "r"(mn));
    return r;
}

__device__ __forceinline__ void hfma2_acc(uint32_t& acc, uint32_t a, uint32_t b) {
    asm("fma.rn.f16x2 %0, %1, %2, %0;" : "+r"(acc) : "r"(a), "r"(b));
}

__global__ void __launch_bounds__(256, 1) rnn_fused(
    const int*   __restrict__ x,     // [16384, 65]
    const float* __restrict__ Win0,  // [2, 64]
    const float* __restrict__ Win1,  // [64, 64]
    const float* __restrict__ Wh,    // [2, 64, 64]
    const float* __restrict__ bvec,  // [2, 64]
    const float* __restrict__ Wlat,  // [64, 2]
    const float* __restrict__ blat,  // [2]
    const float* __restrict__ Wcav,  // [128, 8]
    const float* __restrict__ bcav,  // [8]
    float*       __restrict__ out)   // [16384]
{
    // B-fragment quads: sW4[((l*4+kt)*4+ntp)*32 + lane] =
    //   {frag(nt=2ntp).b0, .b1, frag(nt=2ntp+1).b0, .b1}, lane = 4q+m. LDS.128.
    __shared__ uint4 sW4[3 * 4 * 4 * 32];      // l: 0=Wh0, 1=Win1, 2=Wh1 (24 KB)
    __shared__ float sV[3][72];                // V[b] = Win0[b]+b0 ; V[2] = b0
    __shared__ float sB1[64];                  // b1
    __shared__ float sWlat[64][2];
    __shared__ float sCav[128][8];
    __shared__ float sB[10];                   // [0..7]=bcav, [8..9]=blat

    const int tid = threadIdx.x;

    for (int i = tid; i < 3 * 4 * 4 * 32; i += 256) {
        int lane_ = i & 31, ntp_ = (i >> 5) & 3, kt_ = (i >> 7) & 3, l_ = i >> 9;
        int q_ = lane_ >> 2, m_ = lane_ & 3;
        int k0 = 16 * kt_ + 2 * m_;
        int n0 = 16 * ntp_ + q_;          // nt = 2*ntp
        int n1 = n0 + 8;                  // nt = 2*ntp+1
        const float* src = (l_ == 0) ? Wh : (l_ == 1 ? Win1 : (Wh + 4096));
        uint4 u;
        u.x = pack2(src[k0 * 64 + n0],       src[(k0 + 1) * 64 + n0]);
        u.y = pack2(src[(k0 + 8) * 64 + n0], src[(k0 + 9) * 64 + n0]);
        u.z = pack2(src[k0 * 64 + n1],       src[(k0 + 1) * 64 + n1]);
        u.w = pack2(src[(k0 + 8) * 64 + n1], src[(k0 + 9) * 64 + n1]);
        sW4[i] = u;
    }
    for (int i = tid; i < 128 * 8; i += 256)
        (reinterpret_cast<float*>(sCav))[i] = Wcav[i];
    if (tid < 64) {
        int c = tid;
        float b0c = bvec[c];
        sV[0][c] = Win0[c] + b0c;
        sV[1][c] = Win0[64 + c] + b0c;
        sV[2][c] = b0c;
        sB1[c] = bvec[64 + c];
        sWlat[c][0] = Wlat[2 * c];
        sWlat[c][1] = Wlat[2 * c + 1];
    }
    if (tid < 8) sB[tid] = bcav[tid];
    if (tid < 2) sB[8 + tid] = blat[tid];
    __syncthreads();

    const int lane = tid & 31, warp = tid >> 5;
    const int q = lane >> 2, m = lane & 3;
    const int rowbase = blockIdx.x * 128 + warp * 16;
    const uint4* wp4 = sW4 + lane;  // compile-time offsets from here

    // ---- pin Win1 (l=1) and Wh1 (l=2) fragments in registers: 32 uint4 ----
    uint4 wIn1[16], wH1[16];
#pragma unroll
    for (int kt = 0; kt < 4; kt++)
#pragma unroll
        for (int ntp = 0; ntp < 4; ntp++) {
            wIn1[kt * 4 + ntp] = wp4[((1 * 4 + kt) * 4 + ntp) * 32];
            wH1[kt * 4 + ntp]  = wp4[((2 * 4 + kt) * 4 + ntp) * 32];
        }

    // pack per-row input bits; h in {0,1} -> row = rowbase + q + 8*h
    uint64_t xb[2];
    int xl[2];
#pragma unroll
    for (int rr = 0; rr < 2; rr++) {
        int r = rowbase + q + rr * 8;
        const int* xr = x + r * 65;
        uint64_t bits = 0;
#pragma unroll 8
        for (int t = 0; t < 64; t++)
            bits |= ((uint64_t)(xr[t] & 1)) << t;
        xb[rr] = bits;
        xl[rr] = xr[64] & 7;
    }

    // Wlat as half2 pairs
    uint32_t wl2[8][2];
#pragma unroll
    for (int nt = 0; nt < 8; nt++) {
        int col = 8 * nt + 2 * m;
        wl2[nt][0] = pack2(sWlat[col][0], sWlat[col + 1][0]);
        wl2[nt][1] = pack2(sWlat[col][1], sWlat[col + 1][1]);
    }
    const float bl0 = sB[8], bl1 = sB[9];

    // C-init constants as half2
    uint32_t b1h[8], Vh[2][8];
#pragma unroll
    for (int nt = 0; nt < 8; nt++) {
        int col = 8 * nt + 2 * m;
        b1h[nt]  = pack2(sB1[col], sB1[col + 1]);
        Vh[0][nt] = pack2(sV[0][col], sV[0][col + 1]);
        Vh[1][nt] = pack2(sV[1][col], sV[1][col + 1]);
    }

    // hidden state, packed post-ELU half2
    uint32_t h0d[8][2], h1d[8][2];
#pragma unroll
    for (int nt = 0; nt < 8; nt++) {
        int col = 8 * nt + 2 * m;
        uint32_t v = elu_h2(pack2(sV[2][col], sV[2][col + 1]));  // h0(0)=elu(b0)
        h0d[nt][0] = v; h0d[nt][1] = v;
        h1d[nt][0] = 0u; h1d[nt][1] = 0u;
    }

    float lp[2] = {0.f, 0.f};
    uint32_t d1s[8][2], d2s[8][2];

#pragma unroll 1
    for (int t = 0; t < 65; t++) {
        const bool last = (t == 64);

        // ---- issue Wh0 loads first (latency hidden by register MMAs below) ----
        uint4 wh0[16];
        if (!last) {
#pragma unroll
            for (int kt = 0; kt < 4; kt++)
#pragma unroll
                for (int ntp = 0; ntp < 4; ntp++)
                    wh0[kt * 4 + ntp] = wp4[((0 * 4 + kt) * 4 + ntp) * 32];
        }

        // layer1 part A: d2s = b1 + h1(t-1)@Wh1   (register operands)
#pragma unroll
        for (int ntp = 0; ntp < 4; ntp++) {
            uint4 u = wH1[ntp];
            mmaf16_init(d2s[2 * ntp][0], d2s[2 * ntp][1],
                h1d[0][0], h1d[0][1], h1d[1][0], h1d[1][1], u.x, u.y,
                b1h[2 * ntp], b1h[2 * ntp]);
            mmaf16_init(d2s[2 * ntp + 1][0], d2s[2 * ntp + 1][1],
                h1d[0][0], h1d[0][1], h1d[1][0], h1d[1][1], u.z, u.w,
                b1h[2 * ntp + 1], b1h[2 * ntp + 1]);
        }
#pragma unroll
        for (int kt = 1; kt < 4; kt++)
#pragma unroll
            for (int ntp = 0; ntp < 4; ntp++) {
                uint4 u = wH1[kt * 4 + ntp];
                mmaf16(d2s[2 * ntp][0], d2s[2 * ntp][1],
                    h1d[2 * kt][0], h1d[2 * kt][1],
                    h1d[2 * kt + 1][0], h1d[2 * kt + 1][1], u.x, u.y);
                mmaf16(d2s[2 * ntp + 1][0], d2s[2 * ntp + 1][1],
                    h1d[2 * kt][0], h1d[2 * kt][1],
                    h1d[2 * kt + 1][0], h1d[2 * kt + 1][1], u.z, u.w);
            }

        // layer0(next): d1s = V[x_t] + h0(t)@Wh0   (wh0 from LDS above)
        if (!last) {
            int i0 = (int)((xb[0] >> t) & 1ull);
            int i1 = (int)((xb[1] >> t) & 1ull);
#pragma unroll
            for (int ntp = 0; ntp < 4; ntp++) {
                uint4 u = wh0[ntp];
                mmaf16_init(d1s[2 * ntp][0], d1s[2 * ntp][1],
                    h0d[0][0], h0d[0][1], h0d[1][0], h0d[1][1], u.x, u.y,
                    Vh[i0][2 * ntp], Vh[i1][2 * ntp]);
                mmaf16_init(d1s[2 * ntp + 1][0], d1s[2 * ntp + 1][1],
                    h0d[0][0], h0d[0][1], h0d[1][0], h0d[1][1], u.z, u.w,
                    Vh[i0][2 * ntp + 1], Vh[i1][2 * ntp + 1]);
            }
#pragma unroll
            for (int kt = 1; kt < 4; kt++)
#pragma unroll
                for (int ntp = 0; ntp < 4; ntp++) {
                    uint4 u = wh0[kt * 4 + ntp];
                    mmaf16(d1s[2 * ntp][0], d1s[2 * ntp][1],
                        h0d[2 * kt][0], h0d[2 * kt][1],
                        h0d[2 * kt + 1][0], h0d[2 * kt + 1][1], u.x, u.y);
                    mmaf16(d1s[2 * ntp + 1][0], d1s[2 * ntp + 1][1],
                        h0d[2 * kt][0], h0d[2 * kt][1],
                        h0d[2 * kt + 1][0], h0d[2 * kt + 1][1], u.z, u.w);
                }
        }

        // layer1 part B: d2s += h0(t)@Win1   (register operands)
#pragma unroll
        for (int kt = 0; kt < 4; kt++)
#pragma unroll
            for (int ntp = 0; ntp < 4; ntp++) {
                uint4 u = wIn1[kt * 4 + ntp];
                mmaf16(d2s[2 * ntp][0], d2s[2 * ntp][1],
                    h0d[2 * kt][0], h0d[2 * kt][1],
                    h0d[2 * kt + 1][0], h0d[2 * kt + 1][1], u.x, u.y);
                mmaf16(d2s[2 * ntp + 1][0], d2s[2 * ntp + 1][1],
                    h0d[2 * kt][0], h0d[2 * kt][1],
                    h0d[2 * kt + 1][0], h0d[2 * kt + 1][1], u.z, u.w);
            }

        // ---- head(t-1) from h1d = h1(t-1), in the MMA shadow ----
        if (t > 0) {
#pragma unroll
            for (int h = 0; h < 2; h++) {
                uint32_t za0 = 0u, za1 = 0u;
#pragma unroll
                for (int nt = 0; nt < 8; nt++) {
                    uint32_t u = h1d[nt][h];
                    hfma2_acc(za0, u, wl2[nt][0]);
                    hfma2_acc(za1, u, wl2[nt][1]);
                }
                float2 f0 = __half22float2(*reinterpret_cast<__half2*>(&za0));
                float2 f1 = __half22float2(*reinterpret_cast<__half2*>(&za1));
                float z0 = f0.x + f0.y, z1 = f1.x + f1.y;
                z0 += __shfl_xor_sync(0xffffffffu, z0, 1);
                z0 += __shfl_xor_sync(0xffffffffu, z0, 2);
                z1 += __shfl_xor_sync(0xffffffffu, z1, 1);
                z1 += __shfl_xor_sync(0xffffffffu, z1, 2);
                z0 += bl0; z1 += bl1;
                int bit = (int)((xb[h] >> (t - 1)) & 1ull);
                float mx = fmaxf(z0, z1);
                float lse = mx + __logf(1.f + __expf(-fabsf(z0 - z1)));
                float zsel = bit ? z1 : z0;
                lp[h] += 0.5f * (zsel - lse);
            }
        }

        // ---- activations (in place on D) ----
#pragma unroll
        for (int nt = 0; nt < 8; nt++) {
            h1d[nt][0] = elu_h2(d2s[nt][0]);
            h1d[nt][1] = elu_h2(d2s[nt][1]);
        }
        if (!last) {
#pragma unroll
            for (int nt = 0; nt < 8; nt++) {
                h0d[nt][0] = elu_h2(d1s[nt][0]);
                h0d[nt][1] = elu_h2(d1s[nt][1]);
            }
        }
    }
    // after loop: h0d = h0(64), h1d = h1(64)  (the "extra cell" state hF)

    // ---- cavity head: hF = [h0(64), h1(64)] (128) @ Wcav + bcav ----
#pragma unroll
    for (int h = 0; h < 2; h++) {
        float zc[8];
#pragma unroll
        for (int c = 0; c < 8; c++) zc[c] = 0.f;
#pragma unroll
        for (int nt = 0; nt < 8; nt++) {
            __half2 h2a = *reinterpret_cast<const __half2*>(&h0d[nt][h]);
            __half2 h2b = *reinterpret_cast<const __half2*>(&h1d[nt][h]);
            float v0 = __half2float(__low2half(h2a));
            float v1 = __half2float(__high2half(h2a));
            float a0v = __half2float(__low2half(h2b));
            float a1v = __half2float(__high2half(h2b));
            int col = 8 * nt + 2 * m;
#pragma unroll
            for (int c = 0; c < 8; c++) {
                zc[c] += v0 * sCav[col][c] + v1 * sCav[col + 1][c]
                       + a0v * sCav[64 + col][c] + a1v * sCav[64 + col + 1][c];
            }
        }
#pragma unroll
        for (int c = 0; c < 8; c++) {
            zc[c] += __shfl_xor_sync(0xffffffffu, zc[c], 1);
            zc[c] += __shfl_xor_sync(0xffffffffu, zc[c], 2);
            zc[c] += sB[c];
        }
        float mx = zc[0];
#pragma unroll
        for (int c = 1; c < 8; c++) mx = fmaxf(mx, zc[c]);
        float s = 0.f;
#pragma unroll
        for (int c = 0; c < 8; c++) s += __expf(zc[c] - mx);
        float lse = mx + __logf(s);
        float zsel = zc[0];
#pragma unroll
        for (int c = 1; c < 8; c++) if (xl[h] == c) zsel = zc[c];
        float total = lp[h] + 0.5f * (zsel - lse);
        if (m == 0) {
            int row = rowbase + q + 8 * h;
            out[row] = total;
        }
    }
}

extern "C" void kernel_launch(void* const* d_in, const int* in_sizes, int n_in,
                              void* d_out, int out_size) {
    (void)in_sizes; (void)n_in; (void)out_size;
    const int*   x    = (const int*)d_in[0];
    const float* Win0 = (const float*)d_in[1];
    const float* Win1 = (const float*)d_in[2];
    const float* Wh   = (const float*)d_in[3];
    const float* b    = (const float*)d_in[4];
    const float* Wlat = (const float*)d_in[5];
    const float* blat = (const float*)d_in[6];
    const float* Wcav = (const float*)d_in[7];
    const float* bcav = (const float*)d_in[8];
    float* out = (float*)d_out;
    rnn_fused<<<128, 256>>>(x, Win0, Win1, Wh, b, Wlat, blat, Wcav, bcav, out);
}

// round 9
// speedup vs baseline: 1.3732x; 1.3732x over previous
#include <cuda_runtime.h>
#include <cuda_fp16.h>
#include <stdint.h>

// RNN1DGeneral: B=16384, L=64, H=64, DEPTH=2, D_L=2, D_C=8, LPF=0.5
// R9 = R7 (fp16 D/C accumulators, best 114.9us) + ONLY Wh1 pinned in
// registers (64 regs). R8 pinned two matrices (128 regs) and spilled
// (L2 11.7%); this stays within budget (~204 live regs).

__device__ __forceinline__ void mmaf16(uint32_t& d0, uint32_t& d1,
    uint32_t a0, uint32_t a1, uint32_t a2, uint32_t a3,
    uint32_t b0, uint32_t b1)
{
    asm("mma.sync.aligned.m16n8k16.row.col.f16.f16.f16.f16 "
        "{%0,%1},{%2,%3,%4,%5},{%6,%7},{%0,%1};"
        : "+r"(d0), "+r"(d1)
        : "r"(a0), "r"(a1), "r"(a2), "r"(a3), "r"(b0), "r"(b1));
}

__device__ __forceinline__ void mmaf16_init(uint32_t& d0, uint32_t& d1,
    uint32_t a0, uint32_t a1, uint32_t a2, uint32_t a3,
    uint32_t b0, uint32_t b1, uint32_t c0, uint32_t c1)
{
    asm("mma.sync.aligned.m16n8k16.row.col.f16.f16.f16.f16 "
        "{%0,%1},{%2,%3,%4,%5},{%6,%7},{%8,%9};"
        : "=r"(d0), "=r"(d1)
        : "r"(a0), "r"(a1), "r"(a2), "r"(a3), "r"(b0), "r"(b1),
          "r"(c0), "r"(c1));
}

__device__ __forceinline__ uint32_t pack2(float lo, float hi) {
    __half2 h = __floats2half2_rn(lo, hi);
    return *reinterpret_cast<const uint32_t*>(&h);
}

// elementwise ELU on packed half2: max(v,0) + min(exp(v)-1, 0)
__device__ __forceinline__ uint32_t elu_h2(uint32_t u) {
    const uint32_t LOG2E2 = 0x3DC53DC5u;  // half2(log2e, log2e)
    const uint32_t ONE2   = 0x3C003C00u;  // half2(1, 1)
    uint32_t zero = 0u;
    uint32_t t, e, em1, mx, mn, r;
    asm("mul.rn.f16x2 %0, %1, %2;" : "=r"(t) : "r"(u), "r"(LOG2E2));
    asm("ex2.approx.f16x2 %0, %1;" : "=r"(e) : "r"(t));
    asm("sub.rn.f16x2 %0, %1, %2;" : "=r"(em1) : "r"(e), "r"(ONE2));
    asm("max.f16x2 %0, %1, %2;" : "=r"(mx) : "r"(u), "r"(zero));
    asm("min.f16x2 %0, %1, %2;" : "=r"(mn) : "r"(em1), "r"(zero));
    asm("add.rn.f16x2 %0, %1, %2;" : "=r"(r) : "r"(mx), "r"(mn));
    return r;
}

__device__ __forceinline__ void hfma2_acc(uint32_t& acc, uint32_t a, uint32_t b) {
    asm("fma.rn.f16x2 %0, %1, %2, %0;" : "+r"(acc) : "r"(a), "r"(b));
}

__global__ void __launch_bounds__(256, 1) rnn_fused(
    const int*   __restrict__ x,     // [16384, 65]
    const float* __restrict__ Win0,  // [2, 64]
    const float* __restrict__ Win1,  // [64, 64]
    const float* __restrict__ Wh,    // [2, 64, 64]
    const float* __restrict__ bvec,  // [2, 64]
    const float* __restrict__ Wlat,  // [64, 2]
    const float* __restrict__ blat,  // [2]
    const float* __restrict__ Wcav,  // [128, 8]
    const float* __restrict__ bcav,  // [8]
    float*       __restrict__ out)   // [16384]
{
    // B-fragment quads: sW4[((l*4+kt)*4+ntp)*32 + lane] =
    //   {frag(nt=2ntp).b0, .b1, frag(nt=2ntp+1).b0, .b1}, lane = 4q+m. LDS.128.
    __shared__ uint4 sW4[3 * 4 * 4 * 32];      // l: 0=Wh0, 1=Win1, 2=Wh1 (24 KB)
    __shared__ float sV[3][72];                // V[b] = Win0[b]+b0 ; V[2] = b0
    __shared__ float sB1[64];                  // b1
    __shared__ float sWlat[64][2];
    __shared__ float sCav[128][8];
    __shared__ float sB[10];                   // [0..7]=bcav, [8..9]=blat

    const int tid = threadIdx.x;

    for (int i = tid; i < 3 * 4 * 4 * 32; i += 256) {
        int lane_ = i & 31, ntp_ = (i >> 5) & 3, kt_ = (i >> 7) & 3, l_ = i >> 9;
        int q_ = lane_ >> 2, m_ = lane_ & 3;
        int k0 = 16 * kt_ + 2 * m_;
        int n0 = 16 * ntp_ + q_;          // nt = 2*ntp
        int n1 = n0 + 8;                  // nt = 2*ntp+1
        const float* src = (l_ == 0) ? Wh : (l_ == 1 ? Win1 : (Wh + 4096));
        uint4 u;
        u.x = pack2(src[k0 * 64 + n0],       src[(k0 + 1) * 64 + n0]);
        u.y = pack2(src[(k0 + 8) * 64 + n0], src[(k0 + 9) * 64 + n0]);
        u.z = pack2(src[k0 * 64 + n1],       src[(k0 + 1) * 64 + n1]);
        u.w = pack2(src[(k0 + 8) * 64 + n1], src[(k0 + 9) * 64 + n1]);
        sW4[i] = u;
    }
    for (int i = tid; i < 128 * 8; i += 256)
        (reinterpret_cast<float*>(sCav))[i] = Wcav[i];
    if (tid < 64) {
        int c = tid;
        float b0c = bvec[c];
        sV[0][c] = Win0[c] + b0c;
        sV[1][c] = Win0[64 + c] + b0c;
        sV[2][c] = b0c;
        sB1[c] = bvec[64 + c];
        sWlat[c][0] = Wlat[2 * c];
        sWlat[c][1] = Wlat[2 * c + 1];
    }
    if (tid < 8) sB[tid] = bcav[tid];
    if (tid < 2) sB[8 + tid] = blat[tid];
    __syncthreads();

    const int lane = tid & 31, warp = tid >> 5;
    const int q = lane >> 2, m = lane & 3;
    const int rowbase = blockIdx.x * 128 + warp * 16;
    const uint4* wp4 = sW4 + lane;  // compile-time offsets from here

    // ---- pin ONLY Wh1 (l=2) fragments in registers: 16 uint4 = 64 regs ----
    uint4 wH1[16];
#pragma unroll
    for (int kt = 0; kt < 4; kt++)
#pragma unroll
        for (int ntp = 0; ntp < 4; ntp++)
            wH1[kt * 4 + ntp] = wp4[((2 * 4 + kt) * 4 + ntp) * 32];

    // pack per-row input bits; h in {0,1} -> row = rowbase + q + 8*h
    uint64_t xb[2];
    int xl[2];
#pragma unroll
    for (int rr = 0; rr < 2; rr++) {
        int r = rowbase + q + rr * 8;
        const int* xr = x + r * 65;
        uint64_t bits = 0;
#pragma unroll 8
        for (int t = 0; t < 64; t++)
            bits |= ((uint64_t)(xr[t] & 1)) << t;
        xb[rr] = bits;
        xl[rr] = xr[64] & 7;
    }

    // Wlat as half2 pairs
    uint32_t wl2[8][2];
#pragma unroll
    for (int nt = 0; nt < 8; nt++) {
        int col = 8 * nt + 2 * m;
        wl2[nt][0] = pack2(sWlat[col][0], sWlat[col + 1][0]);
        wl2[nt][1] = pack2(sWlat[col][1], sWlat[col + 1][1]);
    }
    const float bl0 = sB[8], bl1 = sB[9];

    // C-init constants as half2
    uint32_t b1h[8], Vh[2][8];
#pragma unroll
    for (int nt = 0; nt < 8; nt++) {
        int col = 8 * nt + 2 * m;
        b1h[nt]  = pack2(sB1[col], sB1[col + 1]);
        Vh[0][nt] = pack2(sV[0][col], sV[0][col + 1]);
        Vh[1][nt] = pack2(sV[1][col], sV[1][col + 1]);
    }

    // hidden state, packed post-ELU half2
    uint32_t h0d[8][2], h1d[8][2];
#pragma unroll
    for (int nt = 0; nt < 8; nt++) {
        int col = 8 * nt + 2 * m;
        uint32_t v = elu_h2(pack2(sV[2][col], sV[2][col + 1]));  // h0(0)=elu(b0)
        h0d[nt][0] = v; h0d[nt][1] = v;
        h1d[nt][0] = 0u; h1d[nt][1] = 0u;
    }

    float lp[2] = {0.f, 0.f};
    uint32_t d1s[8][2], d2s[8][2];

#pragma unroll 1
    for (int t = 0; t < 65; t++) {
        const bool last = (t == 64);

        // layer1 part A: d2s = b1 + h1(t-1)@Wh1  (register weights — chain head)
#pragma unroll
        for (int ntp = 0; ntp < 4; ntp++) {
            uint4 u = wH1[ntp];
            mmaf16_init(d2s[2 * ntp][0], d2s[2 * ntp][1],
                h1d[0][0], h1d[0][1], h1d[1][0], h1d[1][1], u.x, u.y,
                b1h[2 * ntp], b1h[2 * ntp]);
            mmaf16_init(d2s[2 * ntp + 1][0], d2s[2 * ntp + 1][1],
                h1d[0][0], h1d[0][1], h1d[1][0], h1d[1][1], u.z, u.w,
                b1h[2 * ntp + 1], b1h[2 * ntp + 1]);
        }
#pragma unroll
        for (int kt = 1; kt < 4; kt++)
#pragma unroll
            for (int ntp = 0; ntp < 4; ntp++) {
                uint4 u = wH1[kt * 4 + ntp];
                mmaf16(d2s[2 * ntp][0], d2s[2 * ntp][1],
                    h1d[2 * kt][0], h1d[2 * kt][1],
                    h1d[2 * kt + 1][0], h1d[2 * kt + 1][1], u.x, u.y);
                mmaf16(d2s[2 * ntp + 1][0], d2s[2 * ntp + 1][1],
                    h1d[2 * kt][0], h1d[2 * kt][1],
                    h1d[2 * kt + 1][0], h1d[2 * kt + 1][1], u.z, u.w);
            }

        // layer0(next): d1s = V[x_t] + h0(t)@Wh0  (SMEM weights, hidden by above)
        if (!last) {
            int i0 = (int)((xb[0] >> t) & 1ull);
            int i1 = (int)((xb[1] >> t) & 1ull);
#pragma unroll
            for (int ntp = 0; ntp < 4; ntp++) {
                uint4 u = wp4[((0 * 4 + 0) * 4 + ntp) * 32];
                mmaf16_init(d1s[2 * ntp][0], d1s[2 * ntp][1],
                    h0d[0][0], h0d[0][1], h0d[1][0], h0d[1][1], u.x, u.y,
                    Vh[i0][2 * ntp], Vh[i1][2 * ntp]);
                mmaf16_init(d1s[2 * ntp + 1][0], d1s[2 * ntp + 1][1],
                    h0d[0][0], h0d[0][1], h0d[1][0], h0d[1][1], u.z, u.w,
                    Vh[i0][2 * ntp + 1], Vh[i1][2 * ntp + 1]);
            }
#pragma unroll
            for (int kt = 1; kt < 4; kt++)
#pragma unroll
                for (int ntp = 0; ntp < 4; ntp++) {
                    uint4 u = wp4[((0 * 4 + kt) * 4 + ntp) * 32];
                    mmaf16(d1s[2 * ntp][0], d1s[2 * ntp][1],
                        h0d[2 * kt][0], h0d[2 * kt][1],
                        h0d[2 * kt + 1][0], h0d[2 * kt + 1][1], u.x, u.y);
                    mmaf16(d1s[2 * ntp + 1][0], d1s[2 * ntp + 1][1],
                        h0d[2 * kt][0], h0d[2 * kt][1],
                        h0d[2 * kt + 1][0], h0d[2 * kt + 1][1], u.z, u.w);
                }
        }

        // layer1 part B: d2s += h0(t)@Win1  (SMEM weights)
#pragma unroll
        for (int kt = 0; kt < 4; kt++)
#pragma unroll
            for (int ntp = 0; ntp < 4; ntp++) {
                uint4 u = wp4[((1 * 4 + kt) * 4 + ntp) * 32];
                mmaf16(d2s[2 * ntp][0], d2s[2 * ntp][1],
                    h0d[2 * kt][0], h0d[2 * kt][1],
                    h0d[2 * kt + 1][0], h0d[2 * kt + 1][1], u.x, u.y);
                mmaf16(d2s[2 * ntp + 1][0], d2s[2 * ntp + 1][1],
                    h0d[2 * kt][0], h0d[2 * kt][1],
                    h0d[2 * kt + 1][0], h0d[2 * kt + 1][1], u.z, u.w);
            }

        // ---- head(t-1) from h1d = h1(t-1), in the MMA shadow ----
        if (t > 0) {
#pragma unroll
            for (int h = 0; h < 2; h++) {
                uint32_t za0 = 0u, za1 = 0u;
#pragma unroll
                for (int nt = 0; nt < 8; nt++) {
                    uint32_t u = h1d[nt][h];
                    hfma2_acc(za0, u, wl2[nt][0]);
                    hfma2_acc(za1, u, wl2[nt][1]);
                }
                float2 f0 = __half22float2(*reinterpret_cast<__half2*>(&za0));
                float2 f1 = __half22float2(*reinterpret_cast<__half2*>(&za1));
                float z0 = f0.x + f0.y, z1 = f1.x + f1.y;
                z0 += __shfl_xor_sync(0xffffffffu, z0, 1);
                z0 += __shfl_xor_sync(0xffffffffu, z0, 2);
                z1 += __shfl_xor_sync(0xffffffffu, z1, 1);
                z1 += __shfl_xor_sync(0xffffffffu, z1, 2);
                z0 += bl0; z1 += bl1;
                int bit = (int)((xb[h] >> (t - 1)) & 1ull);
                float mx = fmaxf(z0, z1);
                float lse = mx + __logf(1.f + __expf(-fabsf(z0 - z1)));
                float zsel = bit ? z1 : z0;
                lp[h] += 0.5f * (zsel - lse);
            }
        }

        // ---- activations (in place on D) ----
#pragma unroll
        for (int nt = 0; nt < 8; nt++) {
            h1d[nt][0] = elu_h2(d2s[nt][0]);
            h1d[nt][1] = elu_h2(d2s[nt][1]);
        }
        if (!last) {
#pragma unroll
            for (int nt = 0; nt < 8; nt++) {
                h0d[nt][0] = elu_h2(d1s[nt][0]);
                h0d[nt][1] = elu_h2(d1s[nt][1]);
            }
        }
    }
    // after loop: h0d = h0(64), h1d = h1(64)  (the "extra cell" state hF)

    // ---- cavity head: hF = [h0(64), h1(64)] (128) @ Wcav + bcav ----
#pragma unroll
    for (int h = 0; h < 2; h++) {
        float zc[8];
#pragma unroll
        for (int c = 0; c < 8; c++) zc[c] = 0.f;
#pragma unroll
        for (int nt = 0; nt < 8; nt++) {
            __half2 h2a = *reinterpret_cast<const __half2*>(&h0d[nt][h]);
            __half2 h2b = *reinterpret_cast<const __half2*>(&h1d[nt][h]);
            float v0 = __half2float(__low2half(h2a));
            float v1 = __half2float(__high2half(h2a));
            float a0v = __half2float(__low2half(h2b));
            float a1v = __half2float(__high2half(h2b));
            int col = 8 * nt + 2 * m;
#pragma unroll
            for (int c = 0; c < 8; c++) {
                zc[c] += v0 * sCav[col][c] + v1 * sCav[col + 1][c]
                       + a0v * sCav[64 + col][c] + a1v * sCav[64 + col + 1][c];
            }
        }
#pragma unroll
        for (int c = 0; c < 8; c++) {
            zc[c] += __shfl_xor_sync(0xffffffffu, zc[c], 1);
            zc[c] += __shfl_xor_sync(0xffffffffu, zc[c], 2);
            zc[c] += sB[c];
        }
        float mx = zc[0];
#pragma unroll
        for (int c = 1; c < 8; c++) mx = fmaxf(mx, zc[c]);
        float s = 0.f;
#pragma unroll
        for (int c = 0; c < 8; c++) s += __expf(zc[c] - mx);
        float lse = mx + __logf(s);
        float zsel = zc[0];
#pragma unroll
        for (int c = 1; c < 8; c++) if (xl[h] == c) zsel = zc[c];
        float total = lp[h] + 0.5f * (zsel - lse);
        if (m == 0) {
            int row = rowbase + q + 8 * h;
            out[row] = total;
        }
    }
}

extern "C" void kernel_launch(void* const* d_in, const int* in_sizes, int n_in,
                              void* d_out, int out_size) {
    (void)in_sizes; (void)n_in; (void)out_size;
    const int*   x    = (const int*)d_in[0];
    const float* Win0 = (const float*)d_in[1];
    const float* Win1 = (const float*)d_in[2];
    const float* Wh   = (const float*)d_in[3];
    const float* b    = (const float*)d_in[4];
    const float* Wlat = (const float*)d_in[5];
    const float* blat = (const float*)d_in[6];
    const float* Wcav = (const float*)d_in[7];
    const float* bcav = (const float*)d_in[8];
    float* out = (float*)d_out;
    rnn_fused<<<128, 256>>>(x, Win0, Win1, Wh, b, Wlat, blat, Wcav, bcav, out);
}